// round 15
// baseline (speedup 1.0000x reference)
#include <cuda_runtime.h>
#include <cuda_fp16.h>
#include <cstdint>

// ---------------------------------------------------------------------------
// Conversation_Self_Attention: B=64, S=512, D=DK=DV=512  (sm_103 mma.sync)
//
// R14 algebraic refactor (Gram matrices, -25% FLOPs) + R15: persistent
// grid-stride tile loops on all GEMMs (grid = 2*SMs resident CTAs) to remove
// wave-quantization tails. Mainloop = R11 (392 TF/s proven): fp16 HMMA
// m16n8k16, ldmatrix, 128x128 CTA, 128 thr, BK=64, 3-stage interleaved
// cp.async, frag double-buffer, 2 CTAs/SM.
// ---------------------------------------------------------------------------

#define BM 128
#define BN 128
#define BK 64
#define BKP 72
#define NSTAGE 3
#define THREADS 128
#define TILE_H (BM * BKP)
#define STAGE_H (2 * TILE_H)
#define SMEM_BYTES (NSTAGE * STAGE_H * 2)      // 110592

static const int Bv = 64, Sv = 512;

// scratch (static device arrays: allocation-free contract)
__device__ __align__(128) __half g_SP[64L * 512 * 1024];   // [sent|pos] fp16
__device__ __align__(128) __half g_WT[4L * 512 * 512];     // WkT, WpkT, WqT, WpqT
__device__ __align__(128) __half g_G [3L * 512 * 512];     // G1, G2, Wvh
__device__ __align__(128) __half g_Tc[64L * 512 * 1024];   // T
__device__ __align__(128) __half g_V [64L * 512 * 512];
__device__ __align__(128) __half g_At[64L * 512 * 512];
__device__ float g_S[64L * 512 * 512];                     // scores
__device__ float g_wv[2052];
__device__ float g_corr[2L * 64 * 512];                    // arow[M], bcol[M]

__device__ __forceinline__ uint32_t smem_u32(const void* p) {
    uint32_t a;
    asm("{ .reg .u64 t; cvta.to.shared.u64 t, %1; cvt.u32.u64 %0, t; }" : "=r"(a) : "l"(p));
    return a;
}

#define LDSM_X4(r0, r1, r2, r3, addr)                                  \
    asm volatile("ldmatrix.sync.aligned.m8n8.x4.shared.b16 "           \
                 "{%0, %1, %2, %3}, [%4];"                             \
                 : "=r"(r0), "=r"(r1), "=r"(r2), "=r"(r3) : "r"(addr))

// ---------------- shared GEMM body (R11 mainloop, extended epilogue) --------
// C = (A @ B^T + bias) * alpha + arow_i + bcol_j   (one BM x BN tile)
template <typename OutT>
__device__ __forceinline__ void gemm_body(
    const __half* __restrict__ Ab, int lda,
    const __half* __restrict__ Bb, int ldb,
    const float* __restrict__ bias,
    const float* __restrict__ arow, const float* __restrict__ bcol,
    float alpha,
    OutT* __restrict__ Cb, int ldc, int K,
    int bm, int bn,
    __half* smem)
{
    const int tid  = threadIdx.x;
    const int lane = tid & 31;
    const int warp = tid >> 5;
    const int wm   = warp & 1;
    const int wn   = warp >> 1;

    const int row8 = tid >> 3;
    const int ch   = tid & 7;

    const int g  = lane >> 3;
    const int lr = lane & 7;
    const uint32_t a_base = (uint32_t)(((wm * 64 + (g & 1) * 8 + lr) * BKP) + (g >> 1) * 8) * 2;
    const uint32_t b_base = (uint32_t)(((wn * 64 + (g >> 1) * 8 + lr) * BKP) + (g & 1) * 8) * 2
                          + TILE_H * 2;

    const uint32_t smem0 = smem_u32(smem);

    float acc[4][8][4];
    #pragma unroll
    for (int i = 0; i < 4; i++)
        #pragma unroll
        for (int j = 0; j < 8; j++)
            #pragma unroll
            for (int k = 0; k < 4; k++) acc[i][j][k] = 0.f;

    unsigned afr[2][4][4], bfr[2][8][2];

    auto load_part = [&](int kt, int part) {
        const int st = kt % NSTAGE;
        __half* dA = smem + st * STAGE_H;
        __half* dB = dA + TILE_H;
        const int k0 = kt * BK;
        #pragma unroll
        for (int i = part * 2; i < part * 2 + 2; i++) {
            const int row = row8 + i * 16;
            {
                const __half* gp = Ab + (size_t)(bm + row) * lda + k0 + ch * 8;
                unsigned s = (unsigned)__cvta_generic_to_shared(dA + row * BKP + ch * 8);
                asm volatile("cp.async.cg.shared.global [%0], [%1], 16;\n" :: "r"(s), "l"(gp));
            }
            {
                const __half* gp = Bb + (size_t)(bn + row) * ldb + k0 + ch * 8;
                unsigned s = (unsigned)__cvta_generic_to_shared(dB + row * BKP + ch * 8);
                asm volatile("cp.async.cg.shared.global [%0], [%1], 16;\n" :: "r"(s), "l"(gp));
            }
        }
    };

    auto frag_load = [&](int buf, uint32_t stageAddr, int kb) {
        #pragma unroll
        for (int mt = 0; mt < 4; mt++) {
            const uint32_t ad = stageAddr + a_base + (uint32_t)((mt * 16 * BKP + kb) * 2);
            LDSM_X4(afr[buf][mt][0], afr[buf][mt][1], afr[buf][mt][2], afr[buf][mt][3], ad);
        }
        #pragma unroll
        for (int ntp = 0; ntp < 4; ntp++) {
            const uint32_t bd = stageAddr + b_base + (uint32_t)((ntp * 16 * BKP + kb) * 2);
            LDSM_X4(bfr[buf][2 * ntp][0], bfr[buf][2 * ntp][1],
                    bfr[buf][2 * ntp + 1][0], bfr[buf][2 * ntp + 1][1], bd);
        }
    };

    const int KT = K / BK;
    #pragma unroll
    for (int p = 0; p < 4; p++) load_part(0, p);
    asm volatile("cp.async.commit_group;\n");
    #pragma unroll
    for (int p = 0; p < 4; p++) load_part(1, p);
    asm volatile("cp.async.commit_group;\n");
    asm volatile("cp.async.wait_group 1;\n");
    __syncthreads();
    frag_load(0, smem0, 0);

    for (int kt = 0; kt < KT; kt++) {
        const uint32_t curA = smem0 + (uint32_t)((kt % NSTAGE) * STAGE_H * 2);
        const uint32_t nxtA = smem0 + (uint32_t)(((kt + 1) % NSTAGE) * STAGE_H * 2);

        #pragma unroll
        for (int kk = 0; kk < 4; kk++) {
            const int buf = kk & 1;
            if (kk < 3) {
                frag_load(buf ^ 1, curA, (kk + 1) * 16);
                if (kt + 2 < KT) load_part(kt + 2, kk);
            } else {
                if (kt + 2 < KT) {
                    load_part(kt + 2, 3);
                    asm volatile("cp.async.commit_group;\n");
                }
                if (kt + 1 < KT) {
                    if (kt + 2 < KT) { asm volatile("cp.async.wait_group 1;\n"); }
                    else             { asm volatile("cp.async.wait_group 0;\n"); }
                    __syncthreads();
                    frag_load(buf ^ 1, nxtA, 0);
                }
            }
            #pragma unroll
            for (int mt = 0; mt < 4; mt++)
                #pragma unroll
                for (int nt = 0; nt < 8; nt++) {
                    float* d = acc[mt][nt];
                    asm volatile(
                        "mma.sync.aligned.m16n8k16.row.col.f32.f16.f16.f32 "
                        "{%0,%1,%2,%3}, {%4,%5,%6,%7}, {%8,%9}, {%0,%1,%2,%3};\n"
                        : "+f"(d[0]), "+f"(d[1]), "+f"(d[2]), "+f"(d[3])
                        : "r"(afr[buf][mt][0]), "r"(afr[buf][mt][1]),
                          "r"(afr[buf][mt][2]), "r"(afr[buf][mt][3]),
                          "r"(bfr[buf][nt][0]), "r"(bfr[buf][nt][1]));
                }
        }
    }

    #pragma unroll
    for (int mt = 0; mt < 4; mt++) {
        const int row = bm + wm * 64 + mt * 16 + (lane >> 2);
        float ar0 = 0.f, ar8 = 0.f;
        if (arow) { ar0 = arow[row]; ar8 = arow[row + 8]; }
        #pragma unroll
        for (int nt = 0; nt < 8; nt++) {
            const int col = bn + wn * 64 + nt * 8 + (lane & 3) * 2;
            float b0 = 0.f, b1 = 0.f;
            if (bias) { b0 = bias[col]; b1 = bias[col + 1]; }
            float bc0 = 0.f, bc1 = 0.f;
            if (bcol) { bc0 = bcol[col]; bc1 = bcol[col + 1]; }
            const float* d = acc[mt][nt];
            const float v0 = (d[0] + b0) * alpha + ar0 + bc0;
            const float v1 = (d[1] + b1) * alpha + ar0 + bc1;
            const float v2 = (d[2] + b0) * alpha + ar8 + bc0;
            const float v3 = (d[3] + b1) * alpha + ar8 + bc1;
            if constexpr (sizeof(OutT) == 2) {
                *reinterpret_cast<__half2*>((__half*)Cb + (size_t)(row    ) * ldc + col) =
                    __floats2half2_rn(v0, v1);
                *reinterpret_cast<__half2*>((__half*)Cb + (size_t)(row + 8) * ldc + col) =
                    __floats2half2_rn(v2, v3);
            } else {
                *reinterpret_cast<float2*>((float*)Cb + (size_t)(row    ) * ldc + col) =
                    make_float2(v0, v1);
                *reinterpret_cast<float2*>((float*)Cb + (size_t)(row + 8) * ldc + col) =
                    make_float2(v2, v3);
            }
        }
    }
}

// ---------------- persistent 3-way projection kernel (T1, T2, V) -----------
struct Proj3 {
    const __half* A[3];
    int           lda[3];
    const float*  bias[3];
    __half*       C[3];
    int           ldc[3];
    float         alpha[3];
};

__global__ void __launch_bounds__(THREADS, 2)
gemm_proj(Proj3 p, const __half* __restrict__ W, long wstride, int K,
          int mTiles, int nTiles, int zTiles)
{
    extern __shared__ __half smem[];
    const int perZ = mTiles * nTiles;
    const int total = perZ * zTiles;
    for (int t = blockIdx.x; t < total; t += gridDim.x) {
        const int z  = t / perZ;
        const int r  = t - z * perZ;
        const int bn = (r / mTiles) * BN;
        const int bm = (r - (r / mTiles) * mTiles) * BM;
        gemm_body<__half>(p.A[z], p.lda[z], W + (size_t)z * wstride, 512,
                          p.bias[z], nullptr, nullptr, p.alpha[z],
                          p.C[z], p.ldc[z], K, bm, bn, smem);
        __syncthreads();
    }
}

// ---------------- persistent batched GEMM (z = batch/matrix index) ----------
template <typename OutT>
__global__ void __launch_bounds__(THREADS, 2)
gemm_batch(const __half* __restrict__ A, int lda, long As,
           const __half* __restrict__ B, int ldb, long Bs,
           const float* __restrict__ bias,
           const float* __restrict__ arow, const float* __restrict__ bcol,
           float alpha,
           OutT* __restrict__ C, int ldc, long Cs,
           int K, int mTiles, int nTiles, int zTiles)
{
    extern __shared__ __half smem[];
    const int perZ = mTiles * nTiles;
    const int total = perZ * zTiles;
    for (int t = blockIdx.x; t < total; t += gridDim.x) {
        const int z  = t / perZ;
        const int r  = t - z * perZ;
        const int bn = (r / mTiles) * BN;
        const int bm = (r - (r / mTiles) * mTiles) * BM;
        const float* ar = arow ? arow + (size_t)z * 512 : nullptr;
        const float* bc = bcol ? bcol + (size_t)z * 512 : nullptr;
        gemm_body<OutT>(A + (size_t)z * As, lda, B + (size_t)z * Bs, ldb,
                        bias, ar, bc, alpha, C + (size_t)z * Cs, ldc, K, bm, bn, smem);
        __syncthreads();
    }
}

// ---------------- convert: sent/pos -> SP interleaved, Wv -> fp16 ----------
__global__ void conv_inputs(const float* __restrict__ sent, const float* __restrict__ pos,
                            const float* __restrict__ Wv,
                            __half* __restrict__ SP, __half* __restrict__ Wvh,
                            long nEmb, long nW)
{
    const int y = blockIdx.y;
    long i = ((long)blockIdx.x * blockDim.x + threadIdx.x) * 8;
    const float* x;
    __half* dst;
    if (y < 2) {
        if (i >= nEmb) return;
        x = y ? pos : sent;
        dst = SP + ((i >> 9) * 1024) + (i & 511) + (y ? 512 : 0);
    } else {
        if (i >= nW) return;
        x = Wv;
        dst = Wvh + i;
    }
    const float4 v0 = *reinterpret_cast<const float4*>(x + i);
    const float4 v1 = *reinterpret_cast<const float4*>(x + i + 4);
    __half2 h[4];
    h[0] = __floats2half2_rn(v0.x, v0.y);
    h[1] = __floats2half2_rn(v0.z, v0.w);
    h[2] = __floats2half2_rn(v1.x, v1.y);
    h[3] = __floats2half2_rn(v1.z, v1.w);
    *reinterpret_cast<uint4*>(dst) = *reinterpret_cast<const uint4*>(h);
}

// ---------------- transpose+convert: W fp32 [512x512] -> W^T fp16 ----------
__global__ void transposeW(const float* __restrict__ Wq, const float* __restrict__ Wk,
                           const float* __restrict__ Wpq, const float* __restrict__ Wpk,
                           __half* __restrict__ WT)
{
    const float* src;
    switch (blockIdx.z) {            // out order: WkT, WpkT, WqT, WpqT
        case 0: src = Wk;  break;
        case 1: src = Wpk; break;
        case 2: src = Wq;  break;
        default: src = Wpq; break;
    }
    __half* dst = WT + (size_t)blockIdx.z * 512 * 512;
    __shared__ __half tile[64][65];
    const int r0 = blockIdx.y * 64, c0 = blockIdx.x * 64;
    const int t = threadIdx.x;
    #pragma unroll
    for (int p = 0; p < 16; p++) {
        const int r = (t >> 6) + p * 4;
        const int c = t & 63;
        tile[c][r] = __float2half_rn(src[(size_t)(r0 + r) * 512 + c0 + c]);
    }
    __syncthreads();
    #pragma unroll
    for (int p = 0; p < 16; p++) {
        const int cc = (t >> 6) + p * 4;
        const int rr = t & 63;
        dst[(size_t)(c0 + cc) * 512 + r0 + rr] = tile[cc][rr];
    }
}

// ---------------- bias-correction weight vectors + const + flags -----------
__global__ void wvec(const float* __restrict__ Wq,  const float* __restrict__ bk,
                     const float* __restrict__ Wk,  const float* __restrict__ bq,
                     const float* __restrict__ Wpq, const float* __restrict__ bpk,
                     const float* __restrict__ Wpk, const float* __restrict__ bpq,
                     float* __restrict__ wv)
{
    const int t = threadIdx.x;      // 512
    const float norm = 0.03125f;
    if (blockIdx.x == 2) {
        if (t < 32) {
            float s = 0.f;
            for (int m = t; m < 512; m += 32) s += bq[m] * bk[m] + bpq[m] * bpk[m];
            #pragma unroll
            for (int off = 16; off; off >>= 1) s += __shfl_xor_sync(~0u, s, off);
            if (t == 0) wv[2048] = s * norm;
        }
        return;
    }
    const float *W1, *v1, *W2, *v2;
    float* out;
    if (blockIdx.x == 0) { W1 = Wq; v1 = bk; W2 = Wpq; v2 = bpk; out = wv; }
    else                 { W1 = Wk; v1 = bq; W2 = Wpk; v2 = bpq; out = wv + 1024; }
    float s1 = 0.f, s2 = 0.f;
    for (int m = 0; m < 512; m++) {
        s1 += W1[(size_t)m * 512 + t] * v1[m];
        s2 += W2[(size_t)m * 512 + t] * v2[m];
    }
    out[t]       = s1 * norm;
    out[512 + t] = s2 * norm;
    float any = fabsf(s1) + fabsf(s2);
    #pragma unroll
    for (int off = 16; off; off >>= 1) any += __shfl_xor_sync(~0u, any, off);
    __shared__ float red[16];
    if ((t & 31) == 0) red[t >> 5] = any;
    __syncthreads();
    if (t == 0) {
        float tot = 0.f;
        for (int w = 0; w < 16; w++) tot += red[w];
        wv[2049 + blockIdx.x] = tot;
    }
}

// ---------------- per-row corrections ----------------
__global__ void rowcol(const __half* __restrict__ SP, const float* __restrict__ wv,
                       const float* __restrict__ bias,
                       float* __restrict__ arow, float* __restrict__ bcol)
{
    __shared__ float zf[3];
    if (threadIdx.x == 0) { zf[0] = wv[2049]; zf[1] = wv[2050]; zf[2] = wv[2048]; }
    __syncthreads();
    const int warp = threadIdx.x >> 5, lane = threadIdx.x & 31;
    const long row = (long)blockIdx.x * 4 + (warp >> 1);
    const bool docol = warp & 1;
    if (zf[0] == 0.f && zf[1] == 0.f) {
        if (lane == 0) {
            if (!docol) arow[row] = 0.f;
            else        bcol[row] = bias[row & 511] + zf[2];
        }
        return;
    }
    const float* w = wv + (docol ? 1024 : 0);
    const __half2* sp = reinterpret_cast<const __half2*>(SP + row * 1024);
    float s = 0.f;
    for (int i = lane; i < 512; i += 32) {
        const float2 f = __half22float2(sp[i]);
        s += f.x * w[2 * i] + f.y * w[2 * i + 1];
    }
    #pragma unroll
    for (int off = 16; off; off >>= 1) s += __shfl_xor_sync(~0u, s, off);
    if (lane == 0) {
        if (!docol) arow[row] = s;
        else        bcol[row] = s + bias[row & 511] + zf[2];
    }
}

// ---------------- softmax over 512 (no-max), 2 rows/block ----------------
__global__ void softmax512(const float* __restrict__ S,
                           float* __restrict__ Ofull,
                           __half* __restrict__ Oh)
{
    const int half = threadIdx.x >> 7;
    const int t    = threadIdx.x & 127;
    const long row = (long)blockIdx.x * 2 + half;
    const float4 v = ((const float4*)(S + row * 512))[t];

    const float e0 = __expf(v.x), e1 = __expf(v.y);
    const float e2 = __expf(v.z), e3 = __expf(v.w);
    float s = e0 + e1 + e2 + e3;
    #pragma unroll
    for (int off = 16; off; off >>= 1) s += __shfl_xor_sync(~0u, s, off);
    __shared__ float reds[2][4];
    if ((t & 31) == 0) reds[half][t >> 5] = s;
    __syncthreads();
    s = reds[half][0] + reds[half][1] + reds[half][2] + reds[half][3];

    const float inv = 1.0f / s;
    const float p0 = e0 * inv, p1 = e1 * inv, p2 = e2 * inv, p3 = e3 * inv;
    ((float4*)(Ofull + row * 512))[t] = make_float4(p0, p1, p2, p3);
    __half2 h[2] = { __floats2half2_rn(p0, p1), __floats2half2_rn(p2, p3) };
    ((uint2*)(Oh + row * 512))[t] = *reinterpret_cast<const uint2*>(h);
}

// ---------------- launcher ----------------
extern "C" void kernel_launch(void* const* d_in, const int* in_sizes, int n_in,
                              void* d_out, int out_size)
{
    const float* sent = (const float*)d_in[0];
    const float* pos  = (const float*)d_in[1];
    // d_in[2] = branch_emb: unused by the reference
    const float* Wq   = (const float*)d_in[3];
    const float* bq   = (const float*)d_in[4];
    const float* Wk   = (const float*)d_in[5];
    const float* bk   = (const float*)d_in[6];
    const float* Wv   = (const float*)d_in[7];
    const float* bv   = (const float*)d_in[8];
    const float* Wpq  = (const float*)d_in[9];
    const float* bpq  = (const float*)d_in[10];
    const float* Wpk  = (const float*)d_in[11];
    const float* bpk  = (const float*)d_in[12];
    const float* bias = (const float*)d_in[13];
    float* out = (float*)d_out;

    __half *SP, *WT, *G, *Tc, *V, *At;
    float *Sc, *wv, *corr;
    cudaGetSymbolAddress((void**)&SP,   g_SP);
    cudaGetSymbolAddress((void**)&WT,   g_WT);
    cudaGetSymbolAddress((void**)&G,    g_G);
    cudaGetSymbolAddress((void**)&Tc,   g_Tc);
    cudaGetSymbolAddress((void**)&V,    g_V);
    cudaGetSymbolAddress((void**)&At,   g_At);
    cudaGetSymbolAddress((void**)&Sc,   g_S);
    cudaGetSymbolAddress((void**)&wv,   g_wv);
    cudaGetSymbolAddress((void**)&corr, g_corr);

    cudaFuncSetAttribute(gemm_proj,           cudaFuncAttributeMaxDynamicSharedMemorySize, SMEM_BYTES);
    cudaFuncSetAttribute(gemm_batch<float>,   cudaFuncAttributeMaxDynamicSharedMemorySize, SMEM_BYTES);
    cudaFuncSetAttribute(gemm_batch<__half>,  cudaFuncAttributeMaxDynamicSharedMemorySize, SMEM_BYTES);

    // resident CTA slots (2 CTAs/SM) — deterministic, queried once per call
    int smCount = 0;
    cudaDeviceGetAttribute(&smCount, cudaDevAttrMultiProcessorCount, 0);
    const int slots = smCount * 2;

    const long nEmb = (long)Bv * Sv * 512;
    const long nW   = 512L * 512;
    const float norm = 0.03125f;               // 1/sqrt(2*512), exact pow2
    const long  M     = (long)Bv * Sv;
    const long  rowQK = 512L * 1024;
    const long  rowSS = 512L * 512;

    // Stage 0a: converts (SP = [sent|pos] fp16, Wvh), weight transposes, wvec
    {
        dim3 gc((unsigned)(nEmb / 4096), 3);
        conv_inputs<<<gc, 512>>>(sent, pos, Wv, SP, G + 2 * nW, nEmb, nW);
        dim3 gt(8, 8, 4);
        transposeW<<<gt, 256>>>(Wq, Wk, Wpq, Wpk, WT);
        wvec<<<3, 512>>>(Wq, bk, Wk, bq, Wpq, bpk, Wpk, bpq, wv);
    }

    // Stage 0b: Gram matrices G1 = Wk^T Wq, G2 = Wpk^T Wpq  (fp16 out)
    gemm_batch<__half><<<32, THREADS, SMEM_BYTES>>>(
        WT, 512, nW, WT + 2 * nW, 512, nW,
        nullptr, nullptr, nullptr, 1.f,
        G, 512, nW, 512, 4, 4, 2);

    // Stage 0c: per-row bias corrections (fast path when biases are zero)
    rowcol<<<(unsigned)(M / 4), 256>>>(SP, wv, bias, corr, corr + M);

    // Stage 1: T1, T2, V — persistent tiles (3072 tiles on `slots` CTAs)
    {
        Proj3 p;
        p.A[0] = SP;       p.lda[0] = 1024; p.bias[0] = nullptr; p.C[0] = Tc;       p.ldc[0] = 1024; p.alpha[0] = norm;
        p.A[1] = SP + 512; p.lda[1] = 1024; p.bias[1] = nullptr; p.C[1] = Tc + 512; p.ldc[1] = 1024; p.alpha[1] = norm;
        p.A[2] = SP;       p.lda[2] = 1024; p.bias[2] = bv;      p.C[2] = V;        p.ldc[2] = 512;  p.alpha[2] = 1.f;
        const int tiles = (int)(M / BM) * (512 / BN) * 3;
        gemm_proj<<<(unsigned)(tiles < slots ? tiles : slots), THREADS, SMEM_BYTES>>>(
            p, G, nW, 512, (int)(M / BM), 512 / BN, 3);
    }

    // Stage 2: scores[b] = T_b @ SP_b^T + arow_i + bcol_j  — persistent
    {
        const int tiles = (Sv / BM) * (Sv / BN) * Bv;
        gemm_batch<float><<<(unsigned)(tiles < slots ? tiles : slots), THREADS, SMEM_BYTES>>>(
            Tc, 1024, rowQK, SP, 1024, rowQK,
            nullptr, corr, corr + M, 1.f,
            Sc, 512, rowSS, 1024, Sv / BM, Sv / BN, Bv);
    }

    // Stage 3: softmax -> d_out first half (fp32) + fp16 att
    softmax512<<<(unsigned)(M / 2), 256>>>(Sc, out, At);

    // Stage 4: output[b] = att_b @ V_b^T — persistent
    {
        const int tiles = (Sv / BM) * (Sv / BN) * Bv;
        gemm_batch<float><<<(unsigned)(tiles < slots ? tiles : slots), THREADS, SMEM_BYTES>>>(
            At, 512, rowSS, V, 512, rowSS,
            nullptr, nullptr, nullptr, 1.f,
            out + (long)Bv * rowSS, 512, rowSS, 512, Sv / BM, Sv / BN, Bv);
    }
}

// round 16
// speedup vs baseline: 1.0271x; 1.0271x over previous
#include <cuda_runtime.h>
#include <cuda_fp16.h>
#include <cstdint>

// ---------------------------------------------------------------------------
// Conversation_Self_Attention: B=64, S=512, D=DK=DV=512  (sm_103 mma.sync)
//
// R14 structure (best: 415.8us) + R16: split-K=4 Gram GEMM (128 CTAs, one
// full wave, fp32 partials + tiny reduce) replacing the 32-CTA latency-bound
// G GEMM. Fixed grids (R15 persistence regressed). Mainloop = R11
// (392 TF/s proven): fp16 HMMA m16n8k16, ldmatrix, 128x128 CTA, 128 thr,
// BK=64, 3-stage interleaved cp.async, frag double-buffer, 2 CTAs/SM.
//
//   G1 = Wk^T Wq, G2 = Wpk^T Wpq     (split-K partials -> reduce -> fp16)
//   T  = [ norm*(S@G1^T) | norm*(P@G2^T) ]  fp16  [B*S, 1024]
//   scores[b] = T_b @ [S|P]_b^T + arow_i + bcol_j   (fp32)
//   att = softmax(scores) -> d_out fp32 + fp16 copy; out[b] = att_b @ V_b^T
// ---------------------------------------------------------------------------

#define BM 128
#define BN 128
#define BK 64
#define BKP 72
#define NSTAGE 3
#define THREADS 128
#define TILE_H (BM * BKP)
#define STAGE_H (2 * TILE_H)
#define SMEM_BYTES (NSTAGE * STAGE_H * 2)      // 110592

static const int Bv = 64, Sv = 512;

// scratch (static device arrays: allocation-free contract)
__device__ __align__(128) __half g_SP[64L * 512 * 1024];   // [sent|pos] fp16
__device__ __align__(128) __half g_WT[4L * 512 * 512];     // WkT, WpkT, WqT, WpqT
__device__ __align__(128) __half g_G [3L * 512 * 512];     // G1, G2, Wvh
__device__ __align__(128) float  g_Gp[8L * 512 * 512];     // split-K partials
__device__ __align__(128) __half g_Tc[64L * 512 * 1024];   // T
__device__ __align__(128) __half g_V [64L * 512 * 512];
__device__ __align__(128) __half g_At[64L * 512 * 512];
__device__ float g_S[64L * 512 * 512];                     // scores
__device__ float g_wv[2052];
__device__ float g_corr[2L * 64 * 512];                    // arow[M], bcol[M]

__device__ __forceinline__ uint32_t smem_u32(const void* p) {
    uint32_t a;
    asm("{ .reg .u64 t; cvta.to.shared.u64 t, %1; cvt.u32.u64 %0, t; }" : "=r"(a) : "l"(p));
    return a;
}

#define LDSM_X4(r0, r1, r2, r3, addr)                                  \
    asm volatile("ldmatrix.sync.aligned.m8n8.x4.shared.b16 "           \
                 "{%0, %1, %2, %3}, [%4];"                             \
                 : "=r"(r0), "=r"(r1), "=r"(r2), "=r"(r3) : "r"(addr))

// ---------------- shared GEMM body (R11 mainloop, extended epilogue) --------
// C = (A @ B^T + bias) * alpha + arow_i + bcol_j   (tile from blockIdx.x/y)
template <typename OutT>
__device__ __forceinline__ void gemm_body(
    const __half* __restrict__ Ab, int lda,
    const __half* __restrict__ Bb, int ldb,
    const float* __restrict__ bias,
    const float* __restrict__ arow, const float* __restrict__ bcol,
    float alpha,
    OutT* __restrict__ Cb, int ldc, int K,
    __half* smem)
{
    const int tid  = threadIdx.x;
    const int lane = tid & 31;
    const int warp = tid >> 5;
    const int wm   = warp & 1;
    const int wn   = warp >> 1;

    const int bm = blockIdx.x * BM;
    const int bn = blockIdx.y * BN;

    const int row8 = tid >> 3;
    const int ch   = tid & 7;

    const int g  = lane >> 3;
    const int lr = lane & 7;
    const uint32_t a_base = (uint32_t)(((wm * 64 + (g & 1) * 8 + lr) * BKP) + (g >> 1) * 8) * 2;
    const uint32_t b_base = (uint32_t)(((wn * 64 + (g >> 1) * 8 + lr) * BKP) + (g & 1) * 8) * 2
                          + TILE_H * 2;

    const uint32_t smem0 = smem_u32(smem);

    float acc[4][8][4];
    #pragma unroll
    for (int i = 0; i < 4; i++)
        #pragma unroll
        for (int j = 0; j < 8; j++)
            #pragma unroll
            for (int k = 0; k < 4; k++) acc[i][j][k] = 0.f;

    unsigned afr[2][4][4], bfr[2][8][2];

    auto load_part = [&](int kt, int part) {
        const int st = kt % NSTAGE;
        __half* dA = smem + st * STAGE_H;
        __half* dB = dA + TILE_H;
        const int k0 = kt * BK;
        #pragma unroll
        for (int i = part * 2; i < part * 2 + 2; i++) {
            const int row = row8 + i * 16;
            {
                const __half* gp = Ab + (size_t)(bm + row) * lda + k0 + ch * 8;
                unsigned s = (unsigned)__cvta_generic_to_shared(dA + row * BKP + ch * 8);
                asm volatile("cp.async.cg.shared.global [%0], [%1], 16;\n" :: "r"(s), "l"(gp));
            }
            {
                const __half* gp = Bb + (size_t)(bn + row) * ldb + k0 + ch * 8;
                unsigned s = (unsigned)__cvta_generic_to_shared(dB + row * BKP + ch * 8);
                asm volatile("cp.async.cg.shared.global [%0], [%1], 16;\n" :: "r"(s), "l"(gp));
            }
        }
    };

    auto frag_load = [&](int buf, uint32_t stageAddr, int kb) {
        #pragma unroll
        for (int mt = 0; mt < 4; mt++) {
            const uint32_t ad = stageAddr + a_base + (uint32_t)((mt * 16 * BKP + kb) * 2);
            LDSM_X4(afr[buf][mt][0], afr[buf][mt][1], afr[buf][mt][2], afr[buf][mt][3], ad);
        }
        #pragma unroll
        for (int ntp = 0; ntp < 4; ntp++) {
            const uint32_t bd = stageAddr + b_base + (uint32_t)((ntp * 16 * BKP + kb) * 2);
            LDSM_X4(bfr[buf][2 * ntp][0], bfr[buf][2 * ntp][1],
                    bfr[buf][2 * ntp + 1][0], bfr[buf][2 * ntp + 1][1], bd);
        }
    };

    const int KT = K / BK;
    #pragma unroll
    for (int p = 0; p < 4; p++) load_part(0, p);
    asm volatile("cp.async.commit_group;\n");
    #pragma unroll
    for (int p = 0; p < 4; p++) load_part(1, p);
    asm volatile("cp.async.commit_group;\n");
    asm volatile("cp.async.wait_group 1;\n");
    __syncthreads();
    frag_load(0, smem0, 0);

    for (int kt = 0; kt < KT; kt++) {
        const uint32_t curA = smem0 + (uint32_t)((kt % NSTAGE) * STAGE_H * 2);
        const uint32_t nxtA = smem0 + (uint32_t)(((kt + 1) % NSTAGE) * STAGE_H * 2);

        #pragma unroll
        for (int kk = 0; kk < 4; kk++) {
            const int buf = kk & 1;
            if (kk < 3) {
                frag_load(buf ^ 1, curA, (kk + 1) * 16);
                if (kt + 2 < KT) load_part(kt + 2, kk);
            } else {
                if (kt + 2 < KT) {
                    load_part(kt + 2, 3);
                    asm volatile("cp.async.commit_group;\n");
                }
                if (kt + 1 < KT) {
                    if (kt + 2 < KT) { asm volatile("cp.async.wait_group 1;\n"); }
                    else             { asm volatile("cp.async.wait_group 0;\n"); }
                    __syncthreads();
                    frag_load(buf ^ 1, nxtA, 0);
                }
            }
            #pragma unroll
            for (int mt = 0; mt < 4; mt++)
                #pragma unroll
                for (int nt = 0; nt < 8; nt++) {
                    float* d = acc[mt][nt];
                    asm volatile(
                        "mma.sync.aligned.m16n8k16.row.col.f32.f16.f16.f32 "
                        "{%0,%1,%2,%3}, {%4,%5,%6,%7}, {%8,%9}, {%0,%1,%2,%3};\n"
                        : "+f"(d[0]), "+f"(d[1]), "+f"(d[2]), "+f"(d[3])
                        : "r"(afr[buf][mt][0]), "r"(afr[buf][mt][1]),
                          "r"(afr[buf][mt][2]), "r"(afr[buf][mt][3]),
                          "r"(bfr[buf][nt][0]), "r"(bfr[buf][nt][1]));
                }
        }
    }

    #pragma unroll
    for (int mt = 0; mt < 4; mt++) {
        const int row = bm + wm * 64 + mt * 16 + (lane >> 2);
        float ar0 = 0.f, ar8 = 0.f;
        if (arow) { ar0 = arow[row]; ar8 = arow[row + 8]; }
        #pragma unroll
        for (int nt = 0; nt < 8; nt++) {
            const int col = bn + wn * 64 + nt * 8 + (lane & 3) * 2;
            float b0 = 0.f, b1 = 0.f;
            if (bias) { b0 = bias[col]; b1 = bias[col + 1]; }
            float bc0 = 0.f, bc1 = 0.f;
            if (bcol) { bc0 = bcol[col]; bc1 = bcol[col + 1]; }
            const float* d = acc[mt][nt];
            const float v0 = (d[0] + b0) * alpha + ar0 + bc0;
            const float v1 = (d[1] + b1) * alpha + ar0 + bc1;
            const float v2 = (d[2] + b0) * alpha + ar8 + bc0;
            const float v3 = (d[3] + b1) * alpha + ar8 + bc1;
            if constexpr (sizeof(OutT) == 2) {
                *reinterpret_cast<__half2*>((__half*)Cb + (size_t)(row    ) * ldc + col) =
                    __floats2half2_rn(v0, v1);
                *reinterpret_cast<__half2*>((__half*)Cb + (size_t)(row + 8) * ldc + col) =
                    __floats2half2_rn(v2, v3);
            } else {
                *reinterpret_cast<float2*>((float*)Cb + (size_t)(row    ) * ldc + col) =
                    make_float2(v0, v1);
                *reinterpret_cast<float2*>((float*)Cb + (size_t)(row + 8) * ldc + col) =
                    make_float2(v2, v3);
            }
        }
    }
}

// ---------------- 3-way projection kernel (T1, T2, V) ----------------
struct Proj3 {
    const __half* A[3];
    int           lda[3];
    const float*  bias[3];
    __half*       C[3];
    int           ldc[3];
    float         alpha[3];
};

__global__ void __launch_bounds__(THREADS, 2)
gemm_proj(Proj3 p, const __half* __restrict__ W, long wstride, int K)
{
    extern __shared__ __half smem[];
    const int z = blockIdx.z;
    gemm_body<__half>(p.A[z], p.lda[z], W + (size_t)z * wstride, 512,
                      p.bias[z], nullptr, nullptr, p.alpha[z],
                      p.C[z], p.ldc[z], K, smem);
}

// ---------------- batched GEMM (z = batch index) ----------------
template <typename OutT>
__global__ void __launch_bounds__(THREADS, 2)
gemm_batch(const __half* __restrict__ A, int lda, long As,
           const __half* __restrict__ B, int ldb, long Bs,
           const float* __restrict__ bias,
           const float* __restrict__ arow, const float* __restrict__ bcol,
           float alpha,
           OutT* __restrict__ C, int ldc, long Cs,
           int K)
{
    extern __shared__ __half smem[];
    const int z = blockIdx.z;
    const float* ar = arow ? arow + (size_t)z * 512 : nullptr;
    const float* bc = bcol ? bcol + (size_t)z * 512 : nullptr;
    gemm_body<OutT>(A + (size_t)z * As, lda, B + (size_t)z * Bs, ldb,
                    bias, ar, bc, alpha, C + (size_t)z * Cs, ldc, K, smem);
}

// ---------------- split-K Gram GEMM: Gp[z] = WT_zmat[ks] @ WqT_zmat[ks]^T ----
// z = zmat*4 + split; K=128 per split; fp32 partials.
__global__ void __launch_bounds__(THREADS, 2)
gemm_gram(const __half* __restrict__ WT, float* __restrict__ Gp, long nW)
{
    extern __shared__ __half smem[];
    const int z = blockIdx.z;
    const int zmat = z >> 2;
    const int sp   = z & 3;
    gemm_body<float>(WT + (size_t)zmat * nW + sp * 128, 512,
                     WT + 2 * nW + (size_t)zmat * nW + sp * 128, 512,
                     nullptr, nullptr, nullptr, 1.f,
                     Gp + (size_t)z * nW, 512, 128, smem);
}

// ---------------- reduce split-K partials -> fp16 G ----------------
__global__ void gram_reduce(const float* __restrict__ Gp, __half* __restrict__ G, long nW)
{
    long i = ((long)blockIdx.x * blockDim.x + threadIdx.x) * 4;
    if (i >= 2 * nW) return;
    const int  mat = (int)(i / nW);
    const long off = i - (size_t)mat * nW;
    const float* base = Gp + (size_t)mat * 4 * nW + off;
    float4 s = *reinterpret_cast<const float4*>(base);
    #pragma unroll
    for (int p = 1; p < 4; p++) {
        const float4 v = *reinterpret_cast<const float4*>(base + (size_t)p * nW);
        s.x += v.x; s.y += v.y; s.z += v.z; s.w += v.w;
    }
    __half2 h[2] = { __floats2half2_rn(s.x, s.y), __floats2half2_rn(s.z, s.w) };
    *reinterpret_cast<uint2*>(G + (size_t)mat * nW + off) = *reinterpret_cast<const uint2*>(h);
}

// ---------------- convert: sent/pos -> SP interleaved, Wv -> fp16 ----------
__global__ void conv_inputs(const float* __restrict__ sent, const float* __restrict__ pos,
                            const float* __restrict__ Wv,
                            __half* __restrict__ SP, __half* __restrict__ Wvh,
                            long nEmb, long nW)
{
    const int y = blockIdx.y;
    long i = ((long)blockIdx.x * blockDim.x + threadIdx.x) * 8;
    const float* x;
    __half* dst;
    if (y < 2) {
        if (i >= nEmb) return;
        x = y ? pos : sent;
        dst = SP + ((i >> 9) * 1024) + (i & 511) + (y ? 512 : 0);
    } else {
        if (i >= nW) return;
        x = Wv;
        dst = Wvh + i;
    }
    const float4 v0 = *reinterpret_cast<const float4*>(x + i);
    const float4 v1 = *reinterpret_cast<const float4*>(x + i + 4);
    __half2 h[4];
    h[0] = __floats2half2_rn(v0.x, v0.y);
    h[1] = __floats2half2_rn(v0.z, v0.w);
    h[2] = __floats2half2_rn(v1.x, v1.y);
    h[3] = __floats2half2_rn(v1.z, v1.w);
    *reinterpret_cast<uint4*>(dst) = *reinterpret_cast<const uint4*>(h);
}

// ---------------- transpose+convert: W fp32 [512x512] -> W^T fp16 ----------
__global__ void transposeW(const float* __restrict__ Wq, const float* __restrict__ Wk,
                           const float* __restrict__ Wpq, const float* __restrict__ Wpk,
                           __half* __restrict__ WT)
{
    const float* src;
    switch (blockIdx.z) {            // out order: WkT, WpkT, WqT, WpqT
        case 0: src = Wk;  break;
        case 1: src = Wpk; break;
        case 2: src = Wq;  break;
        default: src = Wpq; break;
    }
    __half* dst = WT + (size_t)blockIdx.z * 512 * 512;
    __shared__ __half tile[64][65];
    const int r0 = blockIdx.y * 64, c0 = blockIdx.x * 64;
    const int t = threadIdx.x;
    #pragma unroll
    for (int p = 0; p < 16; p++) {
        const int r = (t >> 6) + p * 4;
        const int c = t & 63;
        tile[c][r] = __float2half_rn(src[(size_t)(r0 + r) * 512 + c0 + c]);
    }
    __syncthreads();
    #pragma unroll
    for (int p = 0; p < 16; p++) {
        const int cc = (t >> 6) + p * 4;
        const int rr = t & 63;
        dst[(size_t)(c0 + cc) * 512 + r0 + rr] = tile[cc][rr];
    }
}

// ---------------- bias-correction weight vectors + const + flags -----------
__global__ void wvec(const float* __restrict__ Wq,  const float* __restrict__ bk,
                     const float* __restrict__ Wk,  const float* __restrict__ bq,
                     const float* __restrict__ Wpq, const float* __restrict__ bpk,
                     const float* __restrict__ Wpk, const float* __restrict__ bpq,
                     float* __restrict__ wv)
{
    const int t = threadIdx.x;      // 512
    const float norm = 0.03125f;
    if (blockIdx.x == 2) {
        if (t < 32) {
            float s = 0.f;
            for (int m = t; m < 512; m += 32) s += bq[m] * bk[m] + bpq[m] * bpk[m];
            #pragma unroll
            for (int off = 16; off; off >>= 1) s += __shfl_xor_sync(~0u, s, off);
            if (t == 0) wv[2048] = s * norm;
        }
        return;
    }
    const float *W1, *v1, *W2, *v2;
    float* out;
    if (blockIdx.x == 0) { W1 = Wq; v1 = bk; W2 = Wpq; v2 = bpk; out = wv; }
    else                 { W1 = Wk; v1 = bq; W2 = Wpk; v2 = bpq; out = wv + 1024; }
    float s1 = 0.f, s2 = 0.f;
    for (int m = 0; m < 512; m++) {
        s1 += W1[(size_t)m * 512 + t] * v1[m];
        s2 += W2[(size_t)m * 512 + t] * v2[m];
    }
    out[t]       = s1 * norm;
    out[512 + t] = s2 * norm;
    float any = fabsf(s1) + fabsf(s2);
    #pragma unroll
    for (int off = 16; off; off >>= 1) any += __shfl_xor_sync(~0u, any, off);
    __shared__ float red[16];
    if ((t & 31) == 0) red[t >> 5] = any;
    __syncthreads();
    if (t == 0) {
        float tot = 0.f;
        for (int w = 0; w < 16; w++) tot += red[w];
        wv[2049 + blockIdx.x] = tot;
    }
}

// ---------------- per-row corrections ----------------
__global__ void rowcol(const __half* __restrict__ SP, const float* __restrict__ wv,
                       const float* __restrict__ bias,
                       float* __restrict__ arow, float* __restrict__ bcol)
{
    __shared__ float zf[3];
    if (threadIdx.x == 0) { zf[0] = wv[2049]; zf[1] = wv[2050]; zf[2] = wv[2048]; }
    __syncthreads();
    const int warp = threadIdx.x >> 5, lane = threadIdx.x & 31;
    const long row = (long)blockIdx.x * 4 + (warp >> 1);
    const bool docol = warp & 1;
    if (zf[0] == 0.f && zf[1] == 0.f) {
        if (lane == 0) {
            if (!docol) arow[row] = 0.f;
            else        bcol[row] = bias[row & 511] + zf[2];
        }
        return;
    }
    const float* w = wv + (docol ? 1024 : 0);
    const __half2* sp = reinterpret_cast<const __half2*>(SP + row * 1024);
    float s = 0.f;
    for (int i = lane; i < 512; i += 32) {
        const float2 f = __half22float2(sp[i]);
        s += f.x * w[2 * i] + f.y * w[2 * i + 1];
    }
    #pragma unroll
    for (int off = 16; off; off >>= 1) s += __shfl_xor_sync(~0u, s, off);
    if (lane == 0) {
        if (!docol) arow[row] = s;
        else        bcol[row] = s + bias[row & 511] + zf[2];
    }
}

// ---------------- softmax over 512 (no-max), 2 rows/block ----------------
__global__ void softmax512(const float* __restrict__ S,
                           float* __restrict__ Ofull,
                           __half* __restrict__ Oh)
{
    const int half = threadIdx.x >> 7;
    const int t    = threadIdx.x & 127;
    const long row = (long)blockIdx.x * 2 + half;
    const float4 v = ((const float4*)(S + row * 512))[t];

    const float e0 = __expf(v.x), e1 = __expf(v.y);
    const float e2 = __expf(v.z), e3 = __expf(v.w);
    float s = e0 + e1 + e2 + e3;
    #pragma unroll
    for (int off = 16; off; off >>= 1) s += __shfl_xor_sync(~0u, s, off);
    __shared__ float reds[2][4];
    if ((t & 31) == 0) reds[half][t >> 5] = s;
    __syncthreads();
    s = reds[half][0] + reds[half][1] + reds[half][2] + reds[half][3];

    const float inv = 1.0f / s;
    const float p0 = e0 * inv, p1 = e1 * inv, p2 = e2 * inv, p3 = e3 * inv;
    ((float4*)(Ofull + row * 512))[t] = make_float4(p0, p1, p2, p3);
    __half2 h[2] = { __floats2half2_rn(p0, p1), __floats2half2_rn(p2, p3) };
    ((uint2*)(Oh + row * 512))[t] = *reinterpret_cast<const uint2*>(h);
}

// ---------------- launcher ----------------
extern "C" void kernel_launch(void* const* d_in, const int* in_sizes, int n_in,
                              void* d_out, int out_size)
{
    const float* sent = (const float*)d_in[0];
    const float* pos  = (const float*)d_in[1];
    // d_in[2] = branch_emb: unused by the reference
    const float* Wq   = (const float*)d_in[3];
    const float* bq   = (const float*)d_in[4];
    const float* Wk   = (const float*)d_in[5];
    const float* bk   = (const float*)d_in[6];
    const float* Wv   = (const float*)d_in[7];
    const float* bv   = (const float*)d_in[8];
    const float* Wpq  = (const float*)d_in[9];
    const float* bpq  = (const float*)d_in[10];
    const float* Wpk  = (const float*)d_in[11];
    const float* bpk  = (const float*)d_in[12];
    const float* bias = (const float*)d_in[13];
    float* out = (float*)d_out;

    __half *SP, *WT, *G, *Tc, *V, *At;
    float *Gp, *Sc, *wv, *corr;
    cudaGetSymbolAddress((void**)&SP,   g_SP);
    cudaGetSymbolAddress((void**)&WT,   g_WT);
    cudaGetSymbolAddress((void**)&G,    g_G);
    cudaGetSymbolAddress((void**)&Gp,   g_Gp);
    cudaGetSymbolAddress((void**)&Tc,   g_Tc);
    cudaGetSymbolAddress((void**)&V,    g_V);
    cudaGetSymbolAddress((void**)&At,   g_At);
    cudaGetSymbolAddress((void**)&Sc,   g_S);
    cudaGetSymbolAddress((void**)&wv,   g_wv);
    cudaGetSymbolAddress((void**)&corr, g_corr);

    cudaFuncSetAttribute(gemm_proj,          cudaFuncAttributeMaxDynamicSharedMemorySize, SMEM_BYTES);
    cudaFuncSetAttribute(gemm_batch<float>,  cudaFuncAttributeMaxDynamicSharedMemorySize, SMEM_BYTES);
    cudaFuncSetAttribute(gemm_gram,          cudaFuncAttributeMaxDynamicSharedMemorySize, SMEM_BYTES);

    const long nEmb = (long)Bv * Sv * 512;
    const long nW   = 512L * 512;
    const float norm = 0.03125f;               // 1/sqrt(2*512), exact pow2
    const long  M     = (long)Bv * Sv;
    const long  rowQK = 512L * 1024;
    const long  rowSS = 512L * 512;

    // Stage 0a: converts (SP = [sent|pos] fp16, Wvh), weight transposes, wvec
    {
        dim3 gc((unsigned)(nEmb / 4096), 3);
        conv_inputs<<<gc, 512>>>(sent, pos, Wv, SP, G + 2 * nW, nEmb, nW);
        dim3 gt(8, 8, 4);
        transposeW<<<gt, 256>>>(Wq, Wk, Wpq, Wpk, WT);
        wvec<<<3, 512>>>(Wq, bk, Wk, bq, Wpq, bpk, Wpk, bpq, wv);
    }

    // Stage 0b: Gram matrices via split-K=4 (128 CTAs = one full wave)
    {
        dim3 gg(4, 4, 8);
        gemm_gram<<<gg, THREADS, SMEM_BYTES>>>(WT, Gp, nW);
        gram_reduce<<<512, 256>>>(Gp, G, nW);
    }

    // Stage 0c: per-row bias corrections (fast path when biases are zero)
    rowcol<<<(unsigned)(M / 4), 256>>>(SP, wv, bias, corr, corr + M);

    // Stage 1: T1, T2, V in one launch (z selects operand set)
    {
        Proj3 p;
        p.A[0] = SP;       p.lda[0] = 1024; p.bias[0] = nullptr; p.C[0] = Tc;       p.ldc[0] = 1024; p.alpha[0] = norm;
        p.A[1] = SP + 512; p.lda[1] = 1024; p.bias[1] = nullptr; p.C[1] = Tc + 512; p.ldc[1] = 1024; p.alpha[1] = norm;
        p.A[2] = SP;       p.lda[2] = 1024; p.bias[2] = bv;      p.C[2] = V;        p.ldc[2] = 512;  p.alpha[2] = 1.f;
        dim3 g1((unsigned)(M / BM), 512 / BN, 3);
        gemm_proj<<<g1, THREADS, SMEM_BYTES>>>(p, G, nW, 512);
    }

    // Stage 2: scores[b] = T_b @ SP_b^T + arow_i + bcol_j   (K=1024, fp32)
    dim3 g2(Sv / BM, Sv / BN, Bv);
    gemm_batch<float><<<g2, THREADS, SMEM_BYTES>>>(
        Tc, 1024, rowQK, SP, 1024, rowQK,
        nullptr, corr, corr + M, 1.f,
        Sc, 512, rowSS, 1024);

    // Stage 3: softmax -> d_out first half (fp32) + fp16 att
    softmax512<<<(unsigned)(M / 2), 256>>>(Sc, out, At);

    // Stage 4: output[b] = att_b @ V_b^T -> d_out second half
    gemm_batch<float><<<g2, THREADS, SMEM_BYTES>>>(
        At, 512, rowSS, V, 512, rowSS,
        nullptr, nullptr, nullptr, 1.f,
        out + (long)Bv * rowSS, 512, rowSS, 512);
}

// round 17
// speedup vs baseline: 1.0332x; 1.0060x over previous
#include <cuda_runtime.h>
#include <cuda_fp16.h>
#include <cstdint>

// ---------------------------------------------------------------------------
// Conversation_Self_Attention: B=64, S=512, D=DK=DV=512  (sm_103 mma.sync)
//
// R16 structure (best: 414.9us) + R17: fp16 score tensor (stage-2 epilogue
// rounds scores to fp16 after fp32 bias/correction add; softmax reads fp16).
// Saves 64 MB of DRAM traffic around the softmax. Mainloop = R11 (392 TF/s):
// fp16 HMMA m16n8k16, ldmatrix, 128x128 CTA, 128 thr, BK=64, 3-stage
// interleaved cp.async, frag double-buffer, 2 CTAs/SM.
//
//   G1 = Wk^T Wq, G2 = Wpk^T Wpq    (split-K=4 partials -> reduce -> fp16)
//   T  = [ norm*(S@G1^T) | norm*(P@G2^T) ]  fp16  [B*S, 1024]
//   scores[b] = fp16( T_b @ [S|P]_b^T + arow_i + bcol_j )
//   att = softmax(scores) -> d_out fp32 + fp16 copy; out[b] = att_b @ V_b^T
// ---------------------------------------------------------------------------

#define BM 128
#define BN 128
#define BK 64
#define BKP 72
#define NSTAGE 3
#define THREADS 128
#define TILE_H (BM * BKP)
#define STAGE_H (2 * TILE_H)
#define SMEM_BYTES (NSTAGE * STAGE_H * 2)      // 110592

static const int Bv = 64, Sv = 512;

// scratch (static device arrays: allocation-free contract)
__device__ __align__(128) __half g_SP[64L * 512 * 1024];   // [sent|pos] fp16
__device__ __align__(128) __half g_WT[4L * 512 * 512];     // WkT, WpkT, WqT, WpqT
__device__ __align__(128) __half g_G [3L * 512 * 512];     // G1, G2, Wvh
__device__ __align__(128) float  g_Gp[8L * 512 * 512];     // split-K partials
__device__ __align__(128) __half g_Tc[64L * 512 * 1024];   // T
__device__ __align__(128) __half g_V [64L * 512 * 512];
__device__ __align__(128) __half g_At[64L * 512 * 512];    // att fp16
__device__ __align__(128) __half g_Sh[64L * 512 * 512];    // scores fp16
__device__ float g_wv[2052];
__device__ float g_corr[2L * 64 * 512];                    // arow[M], bcol[M]

__device__ __forceinline__ uint32_t smem_u32(const void* p) {
    uint32_t a;
    asm("{ .reg .u64 t; cvta.to.shared.u64 t, %1; cvt.u32.u64 %0, t; }" : "=r"(a) : "l"(p));
    return a;
}

#define LDSM_X4(r0, r1, r2, r3, addr)                                  \
    asm volatile("ldmatrix.sync.aligned.m8n8.x4.shared.b16 "           \
                 "{%0, %1, %2, %3}, [%4];"                             \
                 : "=r"(r0), "=r"(r1), "=r"(r2), "=r"(r3) : "r"(addr))

// ---------------- shared GEMM body (R11 mainloop, extended epilogue) --------
// C = (A @ B^T + bias) * alpha + arow_i + bcol_j   (tile from blockIdx.x/y)
template <typename OutT>
__device__ __forceinline__ void gemm_body(
    const __half* __restrict__ Ab, int lda,
    const __half* __restrict__ Bb, int ldb,
    const float* __restrict__ bias,
    const float* __restrict__ arow, const float* __restrict__ bcol,
    float alpha,
    OutT* __restrict__ Cb, int ldc, int K,
    __half* smem)
{
    const int tid  = threadIdx.x;
    const int lane = tid & 31;
    const int warp = tid >> 5;
    const int wm   = warp & 1;
    const int wn   = warp >> 1;

    const int bm = blockIdx.x * BM;
    const int bn = blockIdx.y * BN;

    const int row8 = tid >> 3;
    const int ch   = tid & 7;

    const int g  = lane >> 3;
    const int lr = lane & 7;
    const uint32_t a_base = (uint32_t)(((wm * 64 + (g & 1) * 8 + lr) * BKP) + (g >> 1) * 8) * 2;
    const uint32_t b_base = (uint32_t)(((wn * 64 + (g >> 1) * 8 + lr) * BKP) + (g & 1) * 8) * 2
                          + TILE_H * 2;

    const uint32_t smem0 = smem_u32(smem);

    float acc[4][8][4];
    #pragma unroll
    for (int i = 0; i < 4; i++)
        #pragma unroll
        for (int j = 0; j < 8; j++)
            #pragma unroll
            for (int k = 0; k < 4; k++) acc[i][j][k] = 0.f;

    unsigned afr[2][4][4], bfr[2][8][2];

    auto load_part = [&](int kt, int part) {
        const int st = kt % NSTAGE;
        __half* dA = smem + st * STAGE_H;
        __half* dB = dA + TILE_H;
        const int k0 = kt * BK;
        #pragma unroll
        for (int i = part * 2; i < part * 2 + 2; i++) {
            const int row = row8 + i * 16;
            {
                const __half* gp = Ab + (size_t)(bm + row) * lda + k0 + ch * 8;
                unsigned s = (unsigned)__cvta_generic_to_shared(dA + row * BKP + ch * 8);
                asm volatile("cp.async.cg.shared.global [%0], [%1], 16;\n" :: "r"(s), "l"(gp));
            }
            {
                const __half* gp = Bb + (size_t)(bn + row) * ldb + k0 + ch * 8;
                unsigned s = (unsigned)__cvta_generic_to_shared(dB + row * BKP + ch * 8);
                asm volatile("cp.async.cg.shared.global [%0], [%1], 16;\n" :: "r"(s), "l"(gp));
            }
        }
    };

    auto frag_load = [&](int buf, uint32_t stageAddr, int kb) {
        #pragma unroll
        for (int mt = 0; mt < 4; mt++) {
            const uint32_t ad = stageAddr + a_base + (uint32_t)((mt * 16 * BKP + kb) * 2);
            LDSM_X4(afr[buf][mt][0], afr[buf][mt][1], afr[buf][mt][2], afr[buf][mt][3], ad);
        }
        #pragma unroll
        for (int ntp = 0; ntp < 4; ntp++) {
            const uint32_t bd = stageAddr + b_base + (uint32_t)((ntp * 16 * BKP + kb) * 2);
            LDSM_X4(bfr[buf][2 * ntp][0], bfr[buf][2 * ntp][1],
                    bfr[buf][2 * ntp + 1][0], bfr[buf][2 * ntp + 1][1], bd);
        }
    };

    const int KT = K / BK;
    #pragma unroll
    for (int p = 0; p < 4; p++) load_part(0, p);
    asm volatile("cp.async.commit_group;\n");
    #pragma unroll
    for (int p = 0; p < 4; p++) load_part(1, p);
    asm volatile("cp.async.commit_group;\n");
    asm volatile("cp.async.wait_group 1;\n");
    __syncthreads();
    frag_load(0, smem0, 0);

    for (int kt = 0; kt < KT; kt++) {
        const uint32_t curA = smem0 + (uint32_t)((kt % NSTAGE) * STAGE_H * 2);
        const uint32_t nxtA = smem0 + (uint32_t)(((kt + 1) % NSTAGE) * STAGE_H * 2);

        #pragma unroll
        for (int kk = 0; kk < 4; kk++) {
            const int buf = kk & 1;
            if (kk < 3) {
                frag_load(buf ^ 1, curA, (kk + 1) * 16);
                if (kt + 2 < KT) load_part(kt + 2, kk);
            } else {
                if (kt + 2 < KT) {
                    load_part(kt + 2, 3);
                    asm volatile("cp.async.commit_group;\n");
                }
                if (kt + 1 < KT) {
                    if (kt + 2 < KT) { asm volatile("cp.async.wait_group 1;\n"); }
                    else             { asm volatile("cp.async.wait_group 0;\n"); }
                    __syncthreads();
                    frag_load(buf ^ 1, nxtA, 0);
                }
            }
            #pragma unroll
            for (int mt = 0; mt < 4; mt++)
                #pragma unroll
                for (int nt = 0; nt < 8; nt++) {
                    float* d = acc[mt][nt];
                    asm volatile(
                        "mma.sync.aligned.m16n8k16.row.col.f32.f16.f16.f32 "
                        "{%0,%1,%2,%3}, {%4,%5,%6,%7}, {%8,%9}, {%0,%1,%2,%3};\n"
                        : "+f"(d[0]), "+f"(d[1]), "+f"(d[2]), "+f"(d[3])
                        : "r"(afr[buf][mt][0]), "r"(afr[buf][mt][1]),
                          "r"(afr[buf][mt][2]), "r"(afr[buf][mt][3]),
                          "r"(bfr[buf][nt][0]), "r"(bfr[buf][nt][1]));
                }
        }
    }

    #pragma unroll
    for (int mt = 0; mt < 4; mt++) {
        const int row = bm + wm * 64 + mt * 16 + (lane >> 2);
        float ar0 = 0.f, ar8 = 0.f;
        if (arow) { ar0 = arow[row]; ar8 = arow[row + 8]; }
        #pragma unroll
        for (int nt = 0; nt < 8; nt++) {
            const int col = bn + wn * 64 + nt * 8 + (lane & 3) * 2;
            float b0 = 0.f, b1 = 0.f;
            if (bias) { b0 = bias[col]; b1 = bias[col + 1]; }
            float bc0 = 0.f, bc1 = 0.f;
            if (bcol) { bc0 = bcol[col]; bc1 = bcol[col + 1]; }
            const float* d = acc[mt][nt];
            const float v0 = (d[0] + b0) * alpha + ar0 + bc0;
            const float v1 = (d[1] + b1) * alpha + ar0 + bc1;
            const float v2 = (d[2] + b0) * alpha + ar8 + bc0;
            const float v3 = (d[3] + b1) * alpha + ar8 + bc1;
            if constexpr (sizeof(OutT) == 2) {
                *reinterpret_cast<__half2*>((__half*)Cb + (size_t)(row    ) * ldc + col) =
                    __floats2half2_rn(v0, v1);
                *reinterpret_cast<__half2*>((__half*)Cb + (size_t)(row + 8) * ldc + col) =
                    __floats2half2_rn(v2, v3);
            } else {
                *reinterpret_cast<float2*>((float*)Cb + (size_t)(row    ) * ldc + col) =
                    make_float2(v0, v1);
                *reinterpret_cast<float2*>((float*)Cb + (size_t)(row + 8) * ldc + col) =
                    make_float2(v2, v3);
            }
        }
    }
}

// ---------------- 3-way projection kernel (T1, T2, V) ----------------
struct Proj3 {
    const __half* A[3];
    int           lda[3];
    const float*  bias[3];
    __half*       C[3];
    int           ldc[3];
    float         alpha[3];
};

__global__ void __launch_bounds__(THREADS, 2)
gemm_proj(Proj3 p, const __half* __restrict__ W, long wstride, int K)
{
    extern __shared__ __half smem[];
    const int z = blockIdx.z;
    gemm_body<__half>(p.A[z], p.lda[z], W + (size_t)z * wstride, 512,
                      p.bias[z], nullptr, nullptr, p.alpha[z],
                      p.C[z], p.ldc[z], K, smem);
}

// ---------------- batched GEMM (z = batch index) ----------------
template <typename OutT>
__global__ void __launch_bounds__(THREADS, 2)
gemm_batch(const __half* __restrict__ A, int lda, long As,
           const __half* __restrict__ B, int ldb, long Bs,
           const float* __restrict__ bias,
           const float* __restrict__ arow, const float* __restrict__ bcol,
           float alpha,
           OutT* __restrict__ C, int ldc, long Cs,
           int K)
{
    extern __shared__ __half smem[];
    const int z = blockIdx.z;
    const float* ar = arow ? arow + (size_t)z * 512 : nullptr;
    const float* bc = bcol ? bcol + (size_t)z * 512 : nullptr;
    gemm_body<OutT>(A + (size_t)z * As, lda, B + (size_t)z * Bs, ldb,
                    bias, ar, bc, alpha, C + (size_t)z * Cs, ldc, K, smem);
}

// ---------------- split-K Gram GEMM ----------------
__global__ void __launch_bounds__(THREADS, 2)
gemm_gram(const __half* __restrict__ WT, float* __restrict__ Gp, long nW)
{
    extern __shared__ __half smem[];
    const int z = blockIdx.z;
    const int zmat = z >> 2;
    const int sp   = z & 3;
    gemm_body<float>(WT + (size_t)zmat * nW + sp * 128, 512,
                     WT + 2 * nW + (size_t)zmat * nW + sp * 128, 512,
                     nullptr, nullptr, nullptr, 1.f,
                     Gp + (size_t)z * nW, 512, 128, smem);
}

// ---------------- reduce split-K partials -> fp16 G ----------------
__global__ void gram_reduce(const float* __restrict__ Gp, __half* __restrict__ G, long nW)
{
    long i = ((long)blockIdx.x * blockDim.x + threadIdx.x) * 4;
    if (i >= 2 * nW) return;
    const int  mat = (int)(i / nW);
    const long off = i - (size_t)mat * nW;
    const float* base = Gp + (size_t)mat * 4 * nW + off;
    float4 s = *reinterpret_cast<const float4*>(base);
    #pragma unroll
    for (int p = 1; p < 4; p++) {
        const float4 v = *reinterpret_cast<const float4*>(base + (size_t)p * nW);
        s.x += v.x; s.y += v.y; s.z += v.z; s.w += v.w;
    }
    __half2 h[2] = { __floats2half2_rn(s.x, s.y), __floats2half2_rn(s.z, s.w) };
    *reinterpret_cast<uint2*>(G + (size_t)mat * nW + off) = *reinterpret_cast<const uint2*>(h);
}

// ---------------- convert: sent/pos -> SP interleaved, Wv -> fp16 ----------
__global__ void conv_inputs(const float* __restrict__ sent, const float* __restrict__ pos,
                            const float* __restrict__ Wv,
                            __half* __restrict__ SP, __half* __restrict__ Wvh,
                            long nEmb, long nW)
{
    const int y = blockIdx.y;
    long i = ((long)blockIdx.x * blockDim.x + threadIdx.x) * 8;
    const float* x;
    __half* dst;
    if (y < 2) {
        if (i >= nEmb) return;
        x = y ? pos : sent;
        dst = SP + ((i >> 9) * 1024) + (i & 511) + (y ? 512 : 0);
    } else {
        if (i >= nW) return;
        x = Wv;
        dst = Wvh + i;
    }
    const float4 v0 = *reinterpret_cast<const float4*>(x + i);
    const float4 v1 = *reinterpret_cast<const float4*>(x + i + 4);
    __half2 h[4];
    h[0] = __floats2half2_rn(v0.x, v0.y);
    h[1] = __floats2half2_rn(v0.z, v0.w);
    h[2] = __floats2half2_rn(v1.x, v1.y);
    h[3] = __floats2half2_rn(v1.z, v1.w);
    *reinterpret_cast<uint4*>(dst) = *reinterpret_cast<const uint4*>(h);
}

// ---------------- transpose+convert: W fp32 [512x512] -> W^T fp16 ----------
__global__ void transposeW(const float* __restrict__ Wq, const float* __restrict__ Wk,
                           const float* __restrict__ Wpq, const float* __restrict__ Wpk,
                           __half* __restrict__ WT)
{
    const float* src;
    switch (blockIdx.z) {            // out order: WkT, WpkT, WqT, WpqT
        case 0: src = Wk;  break;
        case 1: src = Wpk; break;
        case 2: src = Wq;  break;
        default: src = Wpq; break;
    }
    __half* dst = WT + (size_t)blockIdx.z * 512 * 512;
    __shared__ __half tile[64][65];
    const int r0 = blockIdx.y * 64, c0 = blockIdx.x * 64;
    const int t = threadIdx.x;
    #pragma unroll
    for (int p = 0; p < 16; p++) {
        const int r = (t >> 6) + p * 4;
        const int c = t & 63;
        tile[c][r] = __float2half_rn(src[(size_t)(r0 + r) * 512 + c0 + c]);
    }
    __syncthreads();
    #pragma unroll
    for (int p = 0; p < 16; p++) {
        const int cc = (t >> 6) + p * 4;
        const int rr = t & 63;
        dst[(size_t)(c0 + cc) * 512 + r0 + rr] = tile[cc][rr];
    }
}

// ---------------- bias-correction weight vectors + const + flags -----------
__global__ void wvec(const float* __restrict__ Wq,  const float* __restrict__ bk,
                     const float* __restrict__ Wk,  const float* __restrict__ bq,
                     const float* __restrict__ Wpq, const float* __restrict__ bpk,
                     const float* __restrict__ Wpk, const float* __restrict__ bpq,
                     float* __restrict__ wv)
{
    const int t = threadIdx.x;      // 512
    const float norm = 0.03125f;
    if (blockIdx.x == 2) {
        if (t < 32) {
            float s = 0.f;
            for (int m = t; m < 512; m += 32) s += bq[m] * bk[m] + bpq[m] * bpk[m];
            #pragma unroll
            for (int off = 16; off; off >>= 1) s += __shfl_xor_sync(~0u, s, off);
            if (t == 0) wv[2048] = s * norm;
        }
        return;
    }
    const float *W1, *v1, *W2, *v2;
    float* out;
    if (blockIdx.x == 0) { W1 = Wq; v1 = bk; W2 = Wpq; v2 = bpk; out = wv; }
    else                 { W1 = Wk; v1 = bq; W2 = Wpk; v2 = bpq; out = wv + 1024; }
    float s1 = 0.f, s2 = 0.f;
    for (int m = 0; m < 512; m++) {
        s1 += W1[(size_t)m * 512 + t] * v1[m];
        s2 += W2[(size_t)m * 512 + t] * v2[m];
    }
    out[t]       = s1 * norm;
    out[512 + t] = s2 * norm;
    float any = fabsf(s1) + fabsf(s2);
    #pragma unroll
    for (int off = 16; off; off >>= 1) any += __shfl_xor_sync(~0u, any, off);
    __shared__ float red[16];
    if ((t & 31) == 0) red[t >> 5] = any;
    __syncthreads();
    if (t == 0) {
        float tot = 0.f;
        for (int w = 0; w < 16; w++) tot += red[w];
        wv[2049 + blockIdx.x] = tot;
    }
}

// ---------------- per-row corrections ----------------
__global__ void rowcol(const __half* __restrict__ SP, const float* __restrict__ wv,
                       const float* __restrict__ bias,
                       float* __restrict__ arow, float* __restrict__ bcol)
{
    __shared__ float zf[3];
    if (threadIdx.x == 0) { zf[0] = wv[2049]; zf[1] = wv[2050]; zf[2] = wv[2048]; }
    __syncthreads();
    const int warp = threadIdx.x >> 5, lane = threadIdx.x & 31;
    const long row = (long)blockIdx.x * 4 + (warp >> 1);
    const bool docol = warp & 1;
    if (zf[0] == 0.f && zf[1] == 0.f) {
        if (lane == 0) {
            if (!docol) arow[row] = 0.f;
            else        bcol[row] = bias[row & 511] + zf[2];
        }
        return;
    }
    const float* w = wv + (docol ? 1024 : 0);
    const __half2* sp = reinterpret_cast<const __half2*>(SP + row * 1024);
    float s = 0.f;
    for (int i = lane; i < 512; i += 32) {
        const float2 f = __half22float2(sp[i]);
        s += f.x * w[2 * i] + f.y * w[2 * i + 1];
    }
    #pragma unroll
    for (int off = 16; off; off >>= 1) s += __shfl_xor_sync(~0u, s, off);
    if (lane == 0) {
        if (!docol) arow[row] = s;
        else        bcol[row] = s + bias[row & 511] + zf[2];
    }
}

// ---------------- softmax over 512 fp16 scores (no-max), 2 rows/block ------
__global__ void softmax512(const __half* __restrict__ Sh,
                           float* __restrict__ Ofull,
                           __half* __restrict__ Oh)
{
    const int half = threadIdx.x >> 7;
    const int t    = threadIdx.x & 127;
    const long row = (long)blockIdx.x * 2 + half;
    const uint2 raw = ((const uint2*)(Sh + row * 512))[t];
    const float2 f0 = __half22float2(*reinterpret_cast<const __half2*>(&raw.x));
    const float2 f1 = __half22float2(*reinterpret_cast<const __half2*>(&raw.y));

    const float e0 = __expf(f0.x), e1 = __expf(f0.y);
    const float e2 = __expf(f1.x), e3 = __expf(f1.y);
    float s = e0 + e1 + e2 + e3;
    #pragma unroll
    for (int off = 16; off; off >>= 1) s += __shfl_xor_sync(~0u, s, off);
    __shared__ float reds[2][4];
    if ((t & 31) == 0) reds[half][t >> 5] = s;
    __syncthreads();
    s = reds[half][0] + reds[half][1] + reds[half][2] + reds[half][3];

    const float inv = 1.0f / s;
    const float p0 = e0 * inv, p1 = e1 * inv, p2 = e2 * inv, p3 = e3 * inv;
    ((float4*)(Ofull + row * 512))[t] = make_float4(p0, p1, p2, p3);
    __half2 h[2] = { __floats2half2_rn(p0, p1), __floats2half2_rn(p2, p3) };
    ((uint2*)(Oh + row * 512))[t] = *reinterpret_cast<const uint2*>(h);
}

// ---------------- launcher ----------------
extern "C" void kernel_launch(void* const* d_in, const int* in_sizes, int n_in,
                              void* d_out, int out_size)
{
    const float* sent = (const float*)d_in[0];
    const float* pos  = (const float*)d_in[1];
    // d_in[2] = branch_emb: unused by the reference
    const float* Wq   = (const float*)d_in[3];
    const float* bq   = (const float*)d_in[4];
    const float* Wk   = (const float*)d_in[5];
    const float* bk   = (const float*)d_in[6];
    const float* Wv   = (const float*)d_in[7];
    const float* bv   = (const float*)d_in[8];
    const float* Wpq  = (const float*)d_in[9];
    const float* bpq  = (const float*)d_in[10];
    const float* Wpk  = (const float*)d_in[11];
    const float* bpk  = (const float*)d_in[12];
    const float* bias = (const float*)d_in[13];
    float* out = (float*)d_out;

    __half *SP, *WT, *G, *Tc, *V, *At, *Sh;
    float *Gp, *wv, *corr;
    cudaGetSymbolAddress((void**)&SP,   g_SP);
    cudaGetSymbolAddress((void**)&WT,   g_WT);
    cudaGetSymbolAddress((void**)&G,    g_G);
    cudaGetSymbolAddress((void**)&Gp,   g_Gp);
    cudaGetSymbolAddress((void**)&Tc,   g_Tc);
    cudaGetSymbolAddress((void**)&V,    g_V);
    cudaGetSymbolAddress((void**)&At,   g_At);
    cudaGetSymbolAddress((void**)&Sh,   g_Sh);
    cudaGetSymbolAddress((void**)&wv,   g_wv);
    cudaGetSymbolAddress((void**)&corr, g_corr);

    cudaFuncSetAttribute(gemm_proj,          cudaFuncAttributeMaxDynamicSharedMemorySize, SMEM_BYTES);
    cudaFuncSetAttribute(gemm_batch<float>,  cudaFuncAttributeMaxDynamicSharedMemorySize, SMEM_BYTES);
    cudaFuncSetAttribute(gemm_batch<__half>, cudaFuncAttributeMaxDynamicSharedMemorySize, SMEM_BYTES);
    cudaFuncSetAttribute(gemm_gram,          cudaFuncAttributeMaxDynamicSharedMemorySize, SMEM_BYTES);

    const long nEmb = (long)Bv * Sv * 512;
    const long nW   = 512L * 512;
    const float norm = 0.03125f;               // 1/sqrt(2*512), exact pow2
    const long  M     = (long)Bv * Sv;
    const long  rowQK = 512L * 1024;
    const long  rowSS = 512L * 512;

    // Stage 0a: converts (SP = [sent|pos] fp16, Wvh), weight transposes, wvec
    {
        dim3 gc((unsigned)(nEmb / 4096), 3);
        conv_inputs<<<gc, 512>>>(sent, pos, Wv, SP, G + 2 * nW, nEmb, nW);
        dim3 gt(8, 8, 4);
        transposeW<<<gt, 256>>>(Wq, Wk, Wpq, Wpk, WT);
        wvec<<<3, 512>>>(Wq, bk, Wk, bq, Wpq, bpk, Wpk, bpq, wv);
    }

    // Stage 0b: Gram matrices via split-K=4 (128 CTAs = one full wave)
    {
        dim3 gg(4, 4, 8);
        gemm_gram<<<gg, THREADS, SMEM_BYTES>>>(WT, Gp, nW);
        gram_reduce<<<512, 256>>>(Gp, G, nW);
    }

    // Stage 0c: per-row bias corrections (fast path when biases are zero)
    rowcol<<<(unsigned)(M / 4), 256>>>(SP, wv, bias, corr, corr + M);

    // Stage 1: T1, T2, V in one launch (z selects operand set)
    {
        Proj3 p;
        p.A[0] = SP;       p.lda[0] = 1024; p.bias[0] = nullptr; p.C[0] = Tc;       p.ldc[0] = 1024; p.alpha[0] = norm;
        p.A[1] = SP + 512; p.lda[1] = 1024; p.bias[1] = nullptr; p.C[1] = Tc + 512; p.ldc[1] = 1024; p.alpha[1] = norm;
        p.A[2] = SP;       p.lda[2] = 1024; p.bias[2] = bv;      p.C[2] = V;        p.ldc[2] = 512;  p.alpha[2] = 1.f;
        dim3 g1((unsigned)(M / BM), 512 / BN, 3);
        gemm_proj<<<g1, THREADS, SMEM_BYTES>>>(p, G, nW, 512);
    }

    // Stage 2: scores[b] = fp16( T_b @ SP_b^T + arow_i + bcol_j )  (K=1024)
    dim3 g2(Sv / BM, Sv / BN, Bv);
    gemm_batch<__half><<<g2, THREADS, SMEM_BYTES>>>(
        Tc, 1024, rowQK, SP, 1024, rowQK,
        nullptr, corr, corr + M, 1.f,
        Sh, 512, rowSS, 1024);

    // Stage 3: softmax (fp16 in) -> d_out first half (fp32) + fp16 att
    softmax512<<<(unsigned)(M / 2), 256>>>(Sh, out, At);

    // Stage 4: output[b] = att_b @ V_b^T -> d_out second half
    gemm_batch<float><<<g2, THREADS, SMEM_BYTES>>>(
        At, 512, rowSS, V, 512, rowSS,
        nullptr, nullptr, nullptr, 1.f,
        out + (long)Bv * rowSS, 512, rowSS, 512);
}